// round 11
// baseline (speedup 1.0000x reference)
#include <cuda_runtime.h>
#include <cuda_bf16.h>
#include <cstdint>
#include <math.h>

typedef unsigned int u32;
typedef unsigned long long u64;

#define BB   128
#define OSRN 64
#define HW28 784
#define NHALF 451584          // 64*7056

// ---------------- scratch (static device globals; no allocation) ----------------
__device__ float  g_U[OSRN*36];                // U = X L^-T  [o][r<4][d<9]
__device__ float  g_h1[BB*64*196];             // SRN pooled [b][64][196]
__device__ float  g_h2[BB*196*128];            // conv2 raw TRANSPOSED [b][pix][oc]
__device__ float  g_h3[BB*128*49];             // post bn2+relu+avgpool [b][128][49]
__device__ float  g_h4[BB*49*128];             // conv3 raw TRANSPOSED [b][pix][oc]
__device__ float  g_h5[BB*128*16];             // post bn3+relu+maxpool [b][128][16]
__device__ float  g_h6[BB*128*16];             // conv4 raw [b][128][16]
__device__ float  g_xe[BB*128];
__device__ float  g_r[BB*128];
__device__ double g_bnsum[512], g_bnsq[512];
__device__ float  g_scf[128], g_shf[128];
__device__ __nv_bfloat16 g_w2hi[128*576],  g_w2lo[128*576];
__device__ __nv_bfloat16 g_w3hi[128*1152], g_w3lo[128*1152];

// ---------------- PTX helpers (plain sm_100-safe) ----------------
__device__ __forceinline__ u32 s2u(const void* p) {
    u32 a;
    asm("{ .reg .u64 t; cvta.to.shared.u64 t, %1; cvt.u32.u64 %0, t; }" : "=r"(a) : "l"(p));
    return a;
}
__device__ __forceinline__ void ldsm4(u32* a, u32 addr) {
    asm volatile("ldmatrix.sync.aligned.m8n8.x4.shared.b16 {%0,%1,%2,%3}, [%4];"
                 : "=r"(a[0]), "=r"(a[1]), "=r"(a[2]), "=r"(a[3]) : "r"(addr));
}
__device__ __forceinline__ void ldsm2(u32& b0, u32& b1, u32 addr) {
    asm volatile("ldmatrix.sync.aligned.m8n8.x2.shared.b16 {%0,%1}, [%2];"
                 : "=r"(b0), "=r"(b1) : "r"(addr));
}
__device__ __forceinline__ void mma16816(float* c, const u32* a, u32 b0, u32 b1) {
    asm volatile("mma.sync.aligned.m16n8k16.row.col.f32.bf16.bf16.f32 "
                 "{%0,%1,%2,%3},{%4,%5,%6,%7},{%8,%9},{%0,%1,%2,%3};"
                 : "+f"(c[0]), "+f"(c[1]), "+f"(c[2]), "+f"(c[3])
                 : "r"(a[0]), "r"(a[1]), "r"(a[2]), "r"(a[3]), "r"(b0), "r"(b1));
}
__device__ __forceinline__ void fold_ch(const double* sum, const double* sq,
                                        const float* gam, const float* bet,
                                        int c, double n, float& sc, float& sh) {
    double m = sum[c] / n, var = sq[c] / n - m*m;
    double inv = 1.0 / sqrt(var + 1e-5);
    double s = (double)gam[c] * inv;
    sc = (float)s;
    sh = (float)((double)bet[c] - m*s);
}

// ---------------- init: zero stats + build U (fp64 Cholesky) ----------------
__global__ void k_init(const float* __restrict__ srn_w) {
    int tid = threadIdx.x;
    if (tid < 512) { g_bnsum[tid] = 0.0; g_bnsq[tid] = 0.0; }
    if (tid >= OSRN) return;
    int o = tid;
    double X[9][4];
    for (int d = 0; d < 9; d++) {
        X[d][0] = 1.0;
        for (int s = 0; s < 3; s++) X[d][1+s] = (double)srn_w[o*27 + d*3 + s];
    }
    double A[4][4];
    for (int j = 0; j < 4; j++)
        for (int k = 0; k < 4; k++) {
            double s = 0;
            for (int d = 0; d < 9; d++) s += X[d][j]*X[d][k];
            A[j][k] = s;
        }
    double L[4][4] = {};
    for (int j = 0; j < 4; j++) {
        double s = A[j][j];
        for (int k = 0; k < j; k++) s -= L[j][k]*L[j][k];
        L[j][j] = sqrt(s);
        for (int i = j+1; i < 4; i++) {
            double t = A[i][j];
            for (int k = 0; k < j; k++) t -= L[i][k]*L[j][k];
            L[i][j] = t / L[j][j];
        }
    }
    for (int d = 0; d < 9; d++) {
        double u0 = X[d][0] / L[0][0];
        double u1 = (X[d][1] - L[1][0]*u0) / L[1][1];
        double u2 = (X[d][2] - L[2][0]*u0 - L[2][1]*u1) / L[2][2];
        double u3 = (X[d][3] - L[3][0]*u0 - L[3][1]*u1 - L[3][2]*u2) / L[3][3];
        g_U[o*36 + 0*9 + d] = (float)u0;
        g_U[o*36 + 1*9 + d] = (float)u1;
        g_U[o*36 + 2*9 + d] = (float)u2;
        g_U[o*36 + 3*9 + d] = (float)u3;
    }
}

// ---------------- weight split: fp32 -> bf16 hi/lo ----------------
__global__ void k_wsplit(const float* __restrict__ w2, const float* __restrict__ w3) {
    int i = blockIdx.x * blockDim.x + threadIdx.x;
    if (i < 128*576) {
        float v = w2[i];
        __nv_bfloat16 h = __float2bfloat16(v);
        g_w2hi[i] = h;
        g_w2lo[i] = __float2bfloat16(v - __bfloat162float(h));
    } else if (i < 128*576 + 128*1152) {
        int j = i - 128*576;
        float v = w3[j];
        __nv_bfloat16 h = __float2bfloat16(v);
        g_w3hi[j] = h;
        g_w3lo[j] = __float2bfloat16(v - __bfloat162float(h));
    }
}

// ---------------- JAX threefry2x32, bit-exact ----------------
__device__ __forceinline__ unsigned rotl32(unsigned x, int d) { return (x << d) | (x >> (32 - d)); }
__device__ __forceinline__ void tf2x32(unsigned c0, unsigned c1, unsigned& o0, unsigned& o1) {
    const unsigned k0 = 0u, k1 = 42u;
    const unsigned k2 = 0x1BD11BDAu ^ k0 ^ k1;
    unsigned x0 = c0 + k0, x1 = c1 + k1;
#define RND(r) { x0 += x1; x1 = rotl32(x1,(r)); x1 ^= x0; }
    RND(13) RND(15) RND(26) RND(6);  x0 += k1; x1 += k2 + 1u;
    RND(17) RND(29) RND(16) RND(24); x0 += k2; x1 += k0 + 2u;
    RND(13) RND(15) RND(26) RND(6);  x0 += k0; x1 += k1 + 3u;
    RND(17) RND(29) RND(16) RND(24); x0 += k1; x1 += k2 + 4u;
    RND(13) RND(15) RND(26) RND(6);  x0 += k2; x1 += k0 + 5u;
#undef RND
    o0 = x0; o1 = x1;
}
__device__ __forceinline__ float bits_to_noise(unsigned bits) {
    float f = __uint_as_float((bits >> 9) | 0x3F800000u) - 1.0f;
    const float lo = -0.99999994f;
    float u = f * 2.0f + lo;
    u = fmaxf(lo, u);
    return 1e-4f * (1.41421356237309515f * erfinvf(u));
}

// ---------------- fused SRN: one block per image, 512 threads ----------------
__global__ void __launch_bounds__(512) k_srn(const float* __restrict__ x) {
    extern __shared__ float sm[];
    float* sy = sm;            // 7056
    float* sU = sm + 7056;     // 2304
    int b = blockIdx.x;
    int tid = threadIdx.x, lane = tid & 31, warp = tid >> 5;

    for (int i = tid; i < OSRN*36; i += 512) sU[i] = g_U[i];

    const float* xb = x + b * HW28;
    unsigned jb = (unsigned)(b & 63) * 7056u;
    bool hi = (b >= 64);
    for (int l = tid; l < HW28; l += 512) {
        int h = l / 28, w = l % 28;
        float v[9]; float s = 0.f;
#pragma unroll
        for (int d = 0; d < 9; d++) {
            int yy = h + d/3 - 1, xx = w + d%3 - 1;
            float t = (yy >= 0 && yy < 28 && xx >= 0 && xx < 28) ? xb[yy*28 + xx] : 0.f;
            unsigned j = jb + (unsigned)(d*784 + l);
            unsigned o0, o1; tf2x32(j, j + (unsigned)NHALF, o0, o1);
            t += bits_to_noise(hi ? o1 : o0);
            v[d] = t; s += t;
        }
        float m = s / 9.f;
        float ss = 0.f;
#pragma unroll
        for (int d = 0; d < 9; d++) { float e = v[d] - m; ss += e*e; }
        float gg = sqrtf(ss / 8.f);
#pragma unroll
        for (int d = 0; d < 9; d++) sy[l*9 + d] = v[d] / gg;
    }
    __syncthreads();

    const float EM1f    = 0.36787944117144233f;
    const float OneMEM1 = 0.6321205588285577f;
    double s_[4] = {0,0,0,0}, s2_[4] = {0,0,0,0};
    for (int pp = lane; pp < 196; pp += 32) {
        int ph = pp / 14, pw = pp % 14;
        float yv[4][9]; float ny2[4];
#pragma unroll
        for (int px = 0; px < 4; px++) {
            int l = (2*ph + (px >> 1))*28 + 2*pw + (px & 1);
            float n2 = 0.f;
#pragma unroll
            for (int i = 0; i < 9; i++) {
                float t = sy[l*9 + i];
                yv[px][i] = t;
                n2 = fmaf(t, t, n2);
            }
            ny2[px] = n2;
        }
#pragma unroll
        for (int oi = 0; oi < 4; oi++) {
            const float* U = sU + (warp*4 + oi)*36;
            float err[4];
#pragma unroll
            for (int px = 0; px < 4; px++) err[px] = ny2[px];
#pragma unroll
            for (int r = 0; r < 4; r++) {
                float t0 = 0.f, t1 = 0.f, t2 = 0.f, t3 = 0.f;
#pragma unroll
                for (int i = 0; i < 9; i++) {
                    float u = U[r*9 + i];
                    t0 = fmaf(u, yv[0][i], t0);
                    t1 = fmaf(u, yv[1][i], t1);
                    t2 = fmaf(u, yv[2][i], t2);
                    t3 = fmaf(u, yv[3][i], t3);
                }
                err[0] = fmaf(-t0, t0, err[0]);
                err[1] = fmaf(-t1, t1, err[1]);
                err[2] = fmaf(-t2, t2, err[2]);
                err[3] = fmaf(-t3, t3, err[3]);
            }
            float sum = 0.f;
#pragma unroll
            for (int px = 0; px < 4; px++) {
                float er = err[px] * (1.f/9.f);
                float A = (expf(-er) - EM1f) / OneMEM1;
                sum += (A - 0.5f);
            }
            float val = sum * 0.25f;
            g_h1[(b*OSRN + warp*4 + oi)*196 + pp] = val;
            s_[oi] += (double)val; s2_[oi] += (double)val * (double)val;
        }
    }
#pragma unroll
    for (int oi = 0; oi < 4; oi++) {
        double s = s_[oi], s2 = s2_[oi];
#pragma unroll
        for (int st = 16; st > 0; st >>= 1) {
            s  += __shfl_xor_sync(0xffffffffu, s,  st);
            s2 += __shfl_xor_sync(0xffffffffu, s2, st);
        }
        if (lane == 0) {
            atomicAdd(&g_bnsum[warp*4 + oi], s);
            atomicAdd(&g_bnsq[warp*4 + oi],  s2);
        }
    }
}

// ============ conv2 via mma.sync, M-split: grid(2, BB), 224 thr ============
// Block (mh, b): pixel rows [mh*112, mh*112+112), all 128 oc. 7 warps: M16 x N128.
#define C2_A_OFF   0
#define C2_ALO_OFF 16128
#define C2_B_OFF   32256
#define C2_BLO_OFF 50688
#define C2_SMEM    69120

__global__ void __launch_bounds__(224, 2) k_conv2_mma(
    const float* __restrict__ in,
    const __nv_bfloat16* __restrict__ whi, const __nv_bfloat16* __restrict__ wlo,
    const float* __restrict__ bias,
    const double* __restrict__ b1sum, const double* __restrict__ b1sq,
    const float* __restrict__ g1, const float* __restrict__ be1,
    float* __restrict__ out,
    double* __restrict__ gsum, double* __restrict__ gsq) {
    extern __shared__ char dsm[];
    __shared__ float s_sc[64], s_sh[64];
    u32 sbase = s2u(dsm);
    int tid = threadIdx.x, lane = tid & 31, wm = tid >> 5;   // wm 0..6
    int mh = blockIdx.x, b = blockIdx.y;

    if (tid < 64) fold_ch(b1sum, b1sq, g1, be1, tid, (double)(BB*196), s_sc[tid], s_sh[tid]);

    float acc[16][4];
#pragma unroll
    for (int nf = 0; nf < 16; nf++)
#pragma unroll
        for (int j = 0; j < 4; j++) acc[nf][j] = 0.f;

    const float* inb = in + b * 64 * 196;
    __syncthreads();

    for (int ch = 0; ch < 9; ch++) {
        __syncthreads();
        // ---- B (pre-split weights, all 128 oc): uint2 copies ----
        for (int idx = tid; idx < 2048; idx += 224) {
            int row = idx >> 4, c4 = idx & 15;
            int go = row*576 + ch*64 + c4*4;
            *(uint2*)(dsm + C2_B_OFF   + row*144 + c4*8) = *(const uint2*)&whi[go];
            *(uint2*)(dsm + C2_BLO_OFF + row*144 + c4*8) = *(const uint2*)&wlo[go];
        }
        // ---- A (im2col of bn1(h1)), 112 local rows ----
        for (int idx = tid; idx < 112*64; idx += 224) {
            int pl = idx >> 6, col = idx & 63;
            int p = mh*112 + pl;
            if (p < 196) {
                int kk = ch*64 + col;
                int ic = kk / 9;
                int k9 = kk - ic*9;
                int dy = k9 / 3, dx = k9 - dy*3;
                int ph = p / 14, pw = p - ph*14;
                int iy = ph + dy - 1, ix = pw + dx - 1;
                float v = 0.f;
                if ((unsigned)iy < 14u && (unsigned)ix < 14u)
                    v = fmaf(s_sc[ic], inb[ic*196 + iy*14 + ix], s_sh[ic]);
                __nv_bfloat16 h = __float2bfloat16(v);
                __nv_bfloat16 l = __float2bfloat16(v - __bfloat162float(h));
                *(__nv_bfloat16*)(dsm + C2_A_OFF   + pl*144 + col*2) = h;
                *(__nv_bfloat16*)(dsm + C2_ALO_OFF + pl*144 + col*2) = l;
            } else if (ch == 0) {
                *(__nv_bfloat16*)(dsm + C2_A_OFF   + pl*144 + col*2) = __float2bfloat16(0.f);
                *(__nv_bfloat16*)(dsm + C2_ALO_OFF + pl*144 + col*2) = __float2bfloat16(0.f);
            }
        }
        __syncthreads();

        int laneA   = lane & 15;
        int laneAof = (lane >> 4) << 4;
        int laneB   = lane & 7;
        int laneBof = ((lane >> 3) & 1) << 4;
#pragma unroll
        for (int ks = 0; ks < 4; ks++) {
            u32 ah[4], al[4];
            u32 aaddr = sbase + C2_A_OFF + (u32)(wm*16 + laneA)*144 + ks*32 + laneAof;
            ldsm4(ah, aaddr);
            ldsm4(al, aaddr + (C2_ALO_OFF - C2_A_OFF));
#pragma unroll
            for (int nf = 0; nf < 16; nf++) {
                u32 baddr = sbase + C2_B_OFF + (u32)(nf*8 + laneB)*144 + ks*32 + laneBof;
                u32 bh0, bh1, bl0, bl1;
                ldsm2(bh0, bh1, baddr);
                ldsm2(bl0, bl1, baddr + (C2_BLO_OFF - C2_B_OFF));
                mma16816(acc[nf], ah, bh0, bh1);
                mma16816(acc[nf], ah, bl0, bl1);
                mma16816(acc[nf], al, bh0, bh1);
            }
        }
    }

    // ---- epilogue: bias + transposed store + fused bn2 stats ----
#pragma unroll
    for (int nf = 0; nf < 16; nf++) {
        int oc0 = nf*8 + (lane & 3)*2;
        float2 bv = *(const float2*)&bias[oc0];
        double ds0 = 0.0, dq0 = 0.0, ds1 = 0.0, dq1 = 0.0;
        float* c = acc[nf];
        int gp = mh*112 + wm*16 + (lane >> 2);
        if (gp < 196) {
            float v0 = c[0] + bv.x, v1 = c[1] + bv.y;
            *(float2*)&out[(b*196 + gp)*128 + oc0] = make_float2(v0, v1);
            ds0 += (double)v0; dq0 += (double)v0*(double)v0;
            ds1 += (double)v1; dq1 += (double)v1*(double)v1;
        }
        int gp2 = gp + 8;
        if (gp2 < 196) {
            float v0 = c[2] + bv.x, v1 = c[3] + bv.y;
            *(float2*)&out[(b*196 + gp2)*128 + oc0] = make_float2(v0, v1);
            ds0 += (double)v0; dq0 += (double)v0*(double)v0;
            ds1 += (double)v1; dq1 += (double)v1*(double)v1;
        }
#pragma unroll
        for (int st = 4; st <= 16; st <<= 1) {
            ds0 += __shfl_xor_sync(0xffffffffu, ds0, st);
            dq0 += __shfl_xor_sync(0xffffffffu, dq0, st);
            ds1 += __shfl_xor_sync(0xffffffffu, ds1, st);
            dq1 += __shfl_xor_sync(0xffffffffu, dq1, st);
        }
        if ((lane >> 2) == 0) {
            atomicAdd(&gsum[oc0],     ds0);
            atomicAdd(&gsq[oc0],      dq0);
            atomicAdd(&gsum[oc0 + 1], ds1);
            atomicAdd(&gsq[oc0 + 1],  dq1);
        }
    }
}

// ============ conv3 via mma.sync, N-split: grid(2, BB), 128 thr ============
// Block (nh, b): all 49 pix (pad 64), oc [nh*64, nh*64+64). 4 warps: M16 x N64.
#define C3_A_OFF   0
#define C3_ALO_OFF 9216
#define C3_B_OFF   18432
#define C3_BLO_OFF 27648
#define C3_SMEM    36864

__global__ void __launch_bounds__(128, 4) k_conv3_mma(
    const float* __restrict__ in,
    const __nv_bfloat16* __restrict__ whi, const __nv_bfloat16* __restrict__ wlo,
    const float* __restrict__ bias,
    float* __restrict__ out,
    double* __restrict__ gsum, double* __restrict__ gsq) {
    extern __shared__ char dsm[];
    u32 sbase = s2u(dsm);
    int tid = threadIdx.x, lane = tid & 31, wm = tid >> 5;   // wm 0..3
    int nh = blockIdx.x, b = blockIdx.y;

    float acc[8][4];
#pragma unroll
    for (int nf = 0; nf < 8; nf++)
#pragma unroll
        for (int j = 0; j < 4; j++) acc[nf][j] = 0.f;

    const float* inb = in + b * 128 * 49;
    const __nv_bfloat16* whiB = whi + nh*64*1152;
    const __nv_bfloat16* wloB = wlo + nh*64*1152;

    for (int ch = 0; ch < 18; ch++) {
        __syncthreads();
        // ---- B (64 oc x 64 K): uint2 copies ----
        for (int idx = tid; idx < 1024; idx += 128) {
            int row = idx >> 4, c4 = idx & 15;
            int go = row*1152 + ch*64 + c4*4;
            *(uint2*)(dsm + C3_B_OFF   + row*144 + c4*8) = *(const uint2*)&whiB[go];
            *(uint2*)(dsm + C3_BLO_OFF + row*144 + c4*8) = *(const uint2*)&wloB[go];
        }
        // ---- A (im2col of h3): 49 rows ----
        for (int idx = tid; idx < 49*64; idx += 128) {
            int p = idx >> 6, col = idx & 63;
            int kk = ch*64 + col;
            int ic = kk / 9;
            int k9 = kk - ic*9;
            int dy = k9 / 3, dx = k9 - dy*3;
            int ph = p / 7, pw = p - ph*7;
            int iy = ph + dy - 1, ix = pw + dx - 1;
            float v = 0.f;
            if ((unsigned)iy < 7u && (unsigned)ix < 7u)
                v = inb[ic*49 + iy*7 + ix];
            __nv_bfloat16 h = __float2bfloat16(v);
            __nv_bfloat16 l = __float2bfloat16(v - __bfloat162float(h));
            *(__nv_bfloat16*)(dsm + C3_A_OFF   + p*144 + col*2) = h;
            *(__nv_bfloat16*)(dsm + C3_ALO_OFF + p*144 + col*2) = l;
        }
        if (ch == 0) {
            for (int idx = tid; idx < 15*64; idx += 128) {
                int p = 49 + (idx >> 6), col = idx & 63;
                *(__nv_bfloat16*)(dsm + C3_A_OFF   + p*144 + col*2) = __float2bfloat16(0.f);
                *(__nv_bfloat16*)(dsm + C3_ALO_OFF + p*144 + col*2) = __float2bfloat16(0.f);
            }
        }
        __syncthreads();

        int laneA   = lane & 15;
        int laneAof = (lane >> 4) << 4;
        int laneB   = lane & 7;
        int laneBof = ((lane >> 3) & 1) << 4;
#pragma unroll
        for (int ks = 0; ks < 4; ks++) {
            u32 ah[4], al[4];
            u32 aaddr = sbase + C3_A_OFF + (u32)(wm*16 + laneA)*144 + ks*32 + laneAof;
            ldsm4(ah, aaddr);
            ldsm4(al, aaddr + (C3_ALO_OFF - C3_A_OFF));
#pragma unroll
            for (int nf = 0; nf < 8; nf++) {
                u32 baddr = sbase + C3_B_OFF + (u32)(nf*8 + laneB)*144 + ks*32 + laneBof;
                u32 bh0, bh1, bl0, bl1;
                ldsm2(bh0, bh1, baddr);
                ldsm2(bl0, bl1, baddr + (C3_BLO_OFF - C3_B_OFF));
                mma16816(acc[nf], ah, bh0, bh1);
                mma16816(acc[nf], ah, bl0, bl1);
                mma16816(acc[nf], al, bh0, bh1);
            }
        }
    }

#pragma unroll
    for (int nf = 0; nf < 8; nf++) {
        int oc0 = nh*64 + nf*8 + (lane & 3)*2;
        float2 bv = *(const float2*)&bias[oc0];
        double ds0 = 0.0, dq0 = 0.0, ds1 = 0.0, dq1 = 0.0;
        float* c = acc[nf];
        int prow = wm*16 + (lane >> 2);
        if (prow < 49) {
            float v0 = c[0] + bv.x, v1 = c[1] + bv.y;
            *(float2*)&out[(b*49 + prow)*128 + oc0] = make_float2(v0, v1);
            ds0 += (double)v0; dq0 += (double)v0*(double)v0;
            ds1 += (double)v1; dq1 += (double)v1*(double)v1;
        }
        int prow2 = prow + 8;
        if (prow2 < 49) {
            float v0 = c[2] + bv.x, v1 = c[3] + bv.y;
            *(float2*)&out[(b*49 + prow2)*128 + oc0] = make_float2(v0, v1);
            ds0 += (double)v0; dq0 += (double)v0*(double)v0;
            ds1 += (double)v1; dq1 += (double)v1*(double)v1;
        }
#pragma unroll
        for (int st = 4; st <= 16; st <<= 1) {
            ds0 += __shfl_xor_sync(0xffffffffu, ds0, st);
            dq0 += __shfl_xor_sync(0xffffffffu, dq0, st);
            ds1 += __shfl_xor_sync(0xffffffffu, ds1, st);
            dq1 += __shfl_xor_sync(0xffffffffu, dq1, st);
        }
        if ((lane >> 2) == 0) {
            atomicAdd(&gsum[oc0],     ds0);
            atomicAdd(&gsq[oc0],      dq0);
            atomicAdd(&gsum[oc0 + 1], ds1);
            atomicAdd(&gsq[oc0 + 1],  dq1);
        }
    }
}

// ---------------- direct 3x3 conv (SIMT) for conv4 ----------------
template<int HH, int WW, int IC, int BPB, int PSLOTS, int PITER>
__global__ void k_conv(const float* __restrict__ in, const float* __restrict__ wt,
                       const float* __restrict__ bias,
                       float* __restrict__ out,
                       double* __restrict__ gsum, double* __restrict__ gsq) {
    constexpr int OC = 128, OCB = 16, PW = WW + 2, TILE = (HH+2)*PW, NPIX = HH*WW, ICC = 8;
    constexpr int REDW = (PSLOTS < 32) ? PSLOTS : 32;
    __shared__ float sIn[BPB][ICC][TILE];
    __shared__ float sW[ICC][9][OCB];
    __shared__ double sS[OCB], sQ2[OCB];
    int tid = threadIdx.x, lane = tid & 31;
    int pslot = tid % PSLOTS;
    int oh = (tid / PSLOTS) & 1;
    int bl = tid / (2*PSLOTS);
    int b0 = blockIdx.x * BPB;
    int oc0 = blockIdx.y * OCB;

    int hh[PITER], wc[PITER]; bool act[PITER];
#pragma unroll
    for (int pi = 0; pi < PITER; pi++) {
        int p = pslot + pi*PSLOTS;
        act[pi] = (p < NPIX);
        if (!act[pi]) p = 0;
        hh[pi] = p / WW; wc[pi] = p % WW;
    }
    float acc[PITER][8];
#pragma unroll
    for (int pi = 0; pi < PITER; pi++)
#pragma unroll
        for (int j = 0; j < 8; j++) acc[pi][j] = 0.f;

    for (int ic0 = 0; ic0 < IC; ic0 += ICC) {
        __syncthreads();
        for (int idx = tid; idx < BPB*ICC*TILE; idx += blockDim.x) {
            int t = idx % TILE; int ic = (idx/TILE) % ICC; int bb = idx/(TILE*ICC);
            int y = t / PW, xx = t % PW;
            float v = 0.f;
            if (y >= 1 && y <= HH && xx >= 1 && xx <= WW)
                v = in[((b0+bb)*IC + ic0+ic)*NPIX + (y-1)*WW + (xx-1)];
            sIn[bb][ic][t] = v;
        }
        for (int idx = tid; idx < ICC*9*OCB; idx += blockDim.x) {
            int ol = idx % OCB; int k = (idx/OCB) % 9; int ic = idx/(OCB*9);
            sW[ic][k][ol] = wt[(oc0+ol)*(IC*9) + (ic0+ic)*9 + k];
        }
        __syncthreads();
#pragma unroll
        for (int ic = 0; ic < ICC; ic++) {
#pragma unroll
            for (int k = 0; k < 9; k++) {
                int dy = k/3, dx = k%3;
                float4 w0 = *(const float4*)&sW[ic][k][oh*8];
                float4 w1 = *(const float4*)&sW[ic][k][oh*8 + 4];
#pragma unroll
                for (int pi = 0; pi < PITER; pi++) {
                    float v = sIn[bl][ic][(hh[pi]+dy)*PW + wc[pi] + dx];
                    acc[pi][0] = fmaf(v, w0.x, acc[pi][0]);
                    acc[pi][1] = fmaf(v, w0.y, acc[pi][1]);
                    acc[pi][2] = fmaf(v, w0.z, acc[pi][2]);
                    acc[pi][3] = fmaf(v, w0.w, acc[pi][3]);
                    acc[pi][4] = fmaf(v, w1.x, acc[pi][4]);
                    acc[pi][5] = fmaf(v, w1.y, acc[pi][5]);
                    acc[pi][6] = fmaf(v, w1.z, acc[pi][6]);
                    acc[pi][7] = fmaf(v, w1.w, acc[pi][7]);
                }
            }
        }
    }

    __syncthreads();
    if (tid < OCB) { sS[tid] = 0.0; sQ2[tid] = 0.0; }
    __syncthreads();

    float bv[8];
#pragma unroll
    for (int j = 0; j < 8; j++) bv[j] = bias[oc0 + oh*8 + j];

    double ds[8], dq[8];
#pragma unroll
    for (int j = 0; j < 8; j++) { ds[j] = 0.0; dq[j] = 0.0; }
#pragma unroll
    for (int pi = 0; pi < PITER; pi++) if (act[pi]) {
        int p = pslot + pi*PSLOTS;
#pragma unroll
        for (int j = 0; j < 8; j++) {
            float v = acc[pi][j] + bv[j];
            out[((b0+bl)*OC + oc0 + oh*8 + j)*NPIX + p] = v;
            double dv = (double)v;
            ds[j] += dv; dq[j] += dv*dv;
        }
    }
#pragma unroll
    for (int st = REDW/2; st > 0; st >>= 1)
#pragma unroll
        for (int j = 0; j < 8; j++) {
            ds[j] += __shfl_xor_sync(0xffffffffu, ds[j], st);
            dq[j] += __shfl_xor_sync(0xffffffffu, dq[j], st);
        }
    if ((lane & (REDW-1)) == 0)
#pragma unroll
        for (int j = 0; j < 8; j++) {
            atomicAdd(&sS[oh*8 + j],  ds[j]);
            atomicAdd(&sQ2[oh*8 + j], dq[j]);
        }
    __syncthreads();
    if (tid < OCB) {
        atomicAdd(&gsum[oc0 + tid], sS[tid]);
        atomicAdd(&gsq[oc0 + tid],  sQ2[tid]);
    }
}

// ---------------- bn2+relu+avgpool2 (reads h2 [b][pix][oc], inline fold) --------
__global__ void k_avgpool_bn_relu(const float* __restrict__ src,
                                  const double* __restrict__ bsum, const double* __restrict__ bsq,
                                  const float* __restrict__ gam, const float* __restrict__ bet,
                                  float* __restrict__ dst) {
    const int HO = 7;
    int i = blockIdx.x * blockDim.x + threadIdx.x;
    if (i >= BB*128*HO*HO) return;
    int c = i & 127;
    int j = i >> 7;
    int pw = j % 7, ph = (j/7) % 7, bb = j/49;
    float a, b2;
    fold_ch(bsum, bsq, gam, bet, c, (double)(BB*196), a, b2);
    float sum = 0.f;
#pragma unroll
    for (int dy = 0; dy < 2; dy++)
#pragma unroll
    for (int dx = 0; dx < 2; dx++) {
        int pix = (2*ph+dy)*14 + 2*pw+dx;
        sum += fmaxf(0.f, fmaf(a, src[(bb*196 + pix)*128 + c], b2));
    }
    dst[(bb*128 + c)*49 + ph*7 + pw] = sum * 0.25f;
}

// ---------------- bn3+relu+maxpool2(pad1) (reads h4 [b][pix][oc], inline fold) --
__global__ void k_maxpool3(const float* __restrict__ src,
                           const double* __restrict__ bsum, const double* __restrict__ bsq,
                           const float* __restrict__ gam, const float* __restrict__ bet,
                           float* __restrict__ dst) {
    int i = blockIdx.x * blockDim.x + threadIdx.x;
    if (i >= BB*128*16) return;
    int pw = i % 4, ph = (i/4) % 4, c = (i/16) % 128, bb = i/(16*128);
    float a, b2;
    fold_ch(bsum, bsq, gam, bet, c, (double)(BB*49), a, b2);
    float m = -1e30f;
#pragma unroll
    for (int dy = 0; dy < 2; dy++) {
        int y = 2*ph - 1 + dy;
        if (y < 0 || y > 6) continue;
#pragma unroll
        for (int dx = 0; dx < 2; dx++) {
            int x = 2*pw - 1 + dx;
            if (x < 0 || x > 6) continue;
            m = fmaxf(m, fmaxf(0.f, fmaf(a, src[(bb*49 + y*7 + x)*128 + c], b2)));
        }
    }
    dst[i] = m;
}

// ---------------- bn4+relu+maxpool4 -> x_errs (inline fold) ----------------
__global__ void k_final_pool(const float* __restrict__ src,
                             const double* __restrict__ bsum, const double* __restrict__ bsq,
                             const float* __restrict__ gam, const float* __restrict__ bet,
                             float* __restrict__ out_err) {
    int i = blockIdx.x * blockDim.x + threadIdx.x;
    if (i >= BB*128) return;
    int c = i % 128;
    const float* p = src + i*16;
    float a, b2;
    fold_ch(bsum, bsq, gam, bet, c, (double)(BB*16), a, b2);
    float m = -1e30f;
#pragma unroll
    for (int k = 0; k < 16; k++) m = fmaxf(m, fmaxf(0.f, fmaf(a, p[k], b2)));
    g_xe[i] = m;
    out_err[i] = m;
}

// ---------------- fc1 ----------------
__global__ void k_fc1(const float* __restrict__ w, const float* __restrict__ bias) {
    __shared__ float xs[128];
    int b = blockIdx.x, o = threadIdx.x;
    xs[o] = g_xe[b*128 + o];
    __syncthreads();
    float a = bias[o];
#pragma unroll 8
    for (int i = 0; i < 128; i++) a = fmaf(w[o*128 + i], xs[i], a);
    g_r[b*128 + o] = a;
}

// ---------------- bnfc ----------------
__global__ void k_bnfc(const float* __restrict__ gam, const float* __restrict__ bet) {
    int c = threadIdx.x;
    double s = 0, s2 = 0;
    for (int b = 0; b < 128; b++) { double v = (double)g_r[b*128 + c]; s += v; s2 += v*v; }
    double m = s/128.0, var = s2/128.0 - m*m;
    double inv = 1.0 / sqrt(var + 1e-5);
    double scv = (double)gam[c] * inv;
    g_scf[c] = (float)scv;
    g_shf[c] = (float)((double)bet[c] - m*scv);
}

// ---------------- fc2 ----------------
__global__ void k_fc2(const float* __restrict__ w, const float* __restrict__ bias,
                      float* __restrict__ out) {
    __shared__ float as[128];
    int b = blockIdx.x, t = threadIdx.x;
    as[t] = fmaxf(0.f, fmaf(g_scf[t], g_r[b*128 + t], g_shf[t]));
    __syncthreads();
    if (t < 10) {
        float a = bias[t];
#pragma unroll 8
        for (int i = 0; i < 128; i++) a = fmaf(w[t*128 + i], as[i], a);
        out[b*10 + t] = a;
    }
}

// ================================================================================
extern "C" void kernel_launch(void* const* d_in, const int* in_sizes, int n_in,
                              void* d_out, int out_size) {
    const float* x       = (const float*)d_in[0];
    const float* srn_w   = (const float*)d_in[1];
    const float* conv2_w = (const float*)d_in[2];
    const float* conv2_b = (const float*)d_in[3];
    const float* conv3_w = (const float*)d_in[4];
    const float* conv3_b = (const float*)d_in[5];
    const float* conv4_w = (const float*)d_in[6];
    const float* conv4_b = (const float*)d_in[7];
    const float* fc1_w   = (const float*)d_in[8];
    const float* fc1_b   = (const float*)d_in[9];
    const float* fc2_w   = (const float*)d_in[10];
    const float* fc2_b   = (const float*)d_in[11];
    const float* bn1_g   = (const float*)d_in[12];
    const float* bn1_b   = (const float*)d_in[13];
    const float* bn2_g   = (const float*)d_in[14];
    const float* bn2_b   = (const float*)d_in[15];
    const float* bn3_g   = (const float*)d_in[16];
    const float* bn3_b   = (const float*)d_in[17];
    const float* bn4_g   = (const float*)d_in[18];
    const float* bn4_b   = (const float*)d_in[19];
    const float* bnfc_g  = (const float*)d_in[20];
    const float* bnfc_b  = (const float*)d_in[21];
    float* out = (float*)d_out;

    float *h1, *h2, *h3, *h4, *h5, *h6;
    double *bsum, *bsq;
    __nv_bfloat16 *w2hi, *w2lo, *w3hi, *w3lo;
    { void* p;
      cudaGetSymbolAddress(&p, g_h1);  h1  = (float*)p;
      cudaGetSymbolAddress(&p, g_h2);  h2  = (float*)p;
      cudaGetSymbolAddress(&p, g_h3);  h3  = (float*)p;
      cudaGetSymbolAddress(&p, g_h4);  h4  = (float*)p;
      cudaGetSymbolAddress(&p, g_h5);  h5  = (float*)p;
      cudaGetSymbolAddress(&p, g_h6);  h6  = (float*)p;
      cudaGetSymbolAddress(&p, g_bnsum); bsum = (double*)p;
      cudaGetSymbolAddress(&p, g_bnsq);  bsq  = (double*)p;
      cudaGetSymbolAddress(&p, g_w2hi); w2hi = (__nv_bfloat16*)p;
      cudaGetSymbolAddress(&p, g_w2lo); w2lo = (__nv_bfloat16*)p;
      cudaGetSymbolAddress(&p, g_w3hi); w3hi = (__nv_bfloat16*)p;
      cudaGetSymbolAddress(&p, g_w3lo); w3lo = (__nv_bfloat16*)p;
    }

    cudaFuncSetAttribute(k_conv2_mma, cudaFuncAttributeMaxDynamicSharedMemorySize, C2_SMEM);
    cudaFuncSetAttribute(k_conv3_mma, cudaFuncAttributeMaxDynamicSharedMemorySize, C3_SMEM);

    k_init<<<1, 512>>>(srn_w);                                              // 1
    k_wsplit<<<(128*576 + 128*1152 + 255)/256, 256>>>(conv2_w, conv3_w);    // 2
    k_srn<<<BB, 512, (7056 + 2304)*sizeof(float)>>>(x);                     // 3
    { dim3 g(2, BB);
      k_conv2_mma<<<g, 224, C2_SMEM>>>(h1, w2hi, w2lo, conv2_b,
                                       bsum, bsq, bn1_g, bn1_b, h2,
                                       bsum + 128, bsq + 128); }            // 4 (profiled)
    k_avgpool_bn_relu<<<(BB*128*49 + 255)/256, 256>>>(h2, bsum + 128, bsq + 128,
                                                      bn2_g, bn2_b, h3);
    { dim3 g(2, BB);
      k_conv3_mma<<<g, 128, C3_SMEM>>>(h3, w3hi, w3lo, conv3_b, h4,
                                       bsum + 256, bsq + 256); }
    k_maxpool3<<<(BB*128*16 + 255)/256, 256>>>(h4, bsum + 256, bsq + 256,
                                               bn3_g, bn3_b, h5);
    { dim3 g(BB/8, 8); k_conv<4,4,128,8,16,1><<<g, 256>>>(h5, conv4_w, conv4_b, h6,
                                                          bsum + 384, bsq + 384); }
    k_final_pool<<<(BB*128 + 255)/256, 256>>>(h6, bsum + 384, bsq + 384,
                                              bn4_g, bn4_b, out + 1280);
    k_fc1<<<BB, 128>>>(fc1_w, fc1_b);
    k_bnfc<<<1, 128>>>(bnfc_g, bnfc_b);
    k_fc2<<<BB, 128>>>(fc2_w, fc2_b, out);
}

// round 12
// speedup vs baseline: 1.1955x; 1.1955x over previous
#include <cuda_runtime.h>
#include <cuda_bf16.h>
#include <cstdint>
#include <math.h>

typedef unsigned int u32;
typedef unsigned long long u64;

#define BB   128
#define OSRN 64
#define HW28 784
#define NHALF 451584          // 64*7056

// ---------------- scratch (static device globals; no allocation) ----------------
__device__ float  g_U[OSRN*36];
__device__ float  g_h1[BB*64*196];             // SRN pooled [b][64][196]
__device__ float  g_h2[BB*196*128];            // conv2 raw TRANSPOSED [b][pix][oc]
__device__ float  g_h3[BB*128*49];             // post bn2+relu+avgpool
__device__ float  g_h4[BB*49*128];             // conv3 raw TRANSPOSED [b][pix][oc]
__device__ float  g_h5[BB*128*16];             // post bn3+relu+maxpool
__device__ float  g_h6[BB*128*16];             // conv4 raw
__device__ float  g_xe[BB*128];
__device__ float  g_r[BB*128];
__device__ double g_bnsum[512], g_bnsq[512];
__device__ float  g_scf[128], g_shf[128];
// prepacked weights: w2 [k9][128 oc][64 ic], w3 [k9][128 oc][128 ic]
__device__ __nv_bfloat16 g_w2hi[9*128*64],  g_w2lo[9*128*64];
__device__ __nv_bfloat16 g_w3hi[9*128*128], g_w3lo[9*128*128];

// ---------------- PTX helpers (plain sm_100-safe) ----------------
__device__ __forceinline__ u32 s2u(const void* p) {
    u32 a;
    asm("{ .reg .u64 t; cvta.to.shared.u64 t, %1; cvt.u32.u64 %0, t; }" : "=r"(a) : "l"(p));
    return a;
}
__device__ __forceinline__ void ldsm4(u32* a, u32 addr) {
    asm volatile("ldmatrix.sync.aligned.m8n8.x4.shared.b16 {%0,%1,%2,%3}, [%4];"
                 : "=r"(a[0]), "=r"(a[1]), "=r"(a[2]), "=r"(a[3]) : "r"(addr));
}
__device__ __forceinline__ void ldsm2(u32& b0, u32& b1, u32 addr) {
    asm volatile("ldmatrix.sync.aligned.m8n8.x2.shared.b16 {%0,%1}, [%2];"
                 : "=r"(b0), "=r"(b1) : "r"(addr));
}
__device__ __forceinline__ void mma16816(float* c, const u32* a, u32 b0, u32 b1) {
    asm volatile("mma.sync.aligned.m16n8k16.row.col.f32.bf16.bf16.f32 "
                 "{%0,%1,%2,%3},{%4,%5,%6,%7},{%8,%9},{%0,%1,%2,%3};"
                 : "+f"(c[0]), "+f"(c[1]), "+f"(c[2]), "+f"(c[3])
                 : "r"(a[0]), "r"(a[1]), "r"(a[2]), "r"(a[3]), "r"(b0), "r"(b1));
}
__device__ __forceinline__ void fold_ch(const double* sum, const double* sq,
                                        const float* gam, const float* bet,
                                        int c, double n, float& sc, float& sh) {
    double m = sum[c] / n, var = sq[c] / n - m*m;
    double inv = 1.0 / sqrt(var + 1e-5);
    double s = (double)gam[c] * inv;
    sc = (float)s;
    sh = (float)((double)bet[c] - m*s);
}

// ---------------- init: zero stats + build U (fp64 Cholesky) ----------------
__global__ void k_init(const float* __restrict__ srn_w) {
    int tid = threadIdx.x;
    if (tid < 512) { g_bnsum[tid] = 0.0; g_bnsq[tid] = 0.0; }
    if (tid >= OSRN) return;
    int o = tid;
    double X[9][4];
    for (int d = 0; d < 9; d++) {
        X[d][0] = 1.0;
        for (int s = 0; s < 3; s++) X[d][1+s] = (double)srn_w[o*27 + d*3 + s];
    }
    double A[4][4];
    for (int j = 0; j < 4; j++)
        for (int k = 0; k < 4; k++) {
            double s = 0;
            for (int d = 0; d < 9; d++) s += X[d][j]*X[d][k];
            A[j][k] = s;
        }
    double L[4][4] = {};
    for (int j = 0; j < 4; j++) {
        double s = A[j][j];
        for (int k = 0; k < j; k++) s -= L[j][k]*L[j][k];
        L[j][j] = sqrt(s);
        for (int i = j+1; i < 4; i++) {
            double t = A[i][j];
            for (int k = 0; k < j; k++) t -= L[i][k]*L[j][k];
            L[i][j] = t / L[j][j];
        }
    }
    for (int d = 0; d < 9; d++) {
        double u0 = X[d][0] / L[0][0];
        double u1 = (X[d][1] - L[1][0]*u0) / L[1][1];
        double u2 = (X[d][2] - L[2][0]*u0 - L[2][1]*u1) / L[2][2];
        double u3 = (X[d][3] - L[3][0]*u0 - L[3][1]*u1 - L[3][2]*u2) / L[3][3];
        g_U[o*36 + 0*9 + d] = (float)u0;
        g_U[o*36 + 1*9 + d] = (float)u1;
        g_U[o*36 + 2*9 + d] = (float)u2;
        g_U[o*36 + 3*9 + d] = (float)u3;
    }
}

// ---------------- weight split + prepack to [k9][oc][ic] ----------------
__global__ void k_wsplit(const float* __restrict__ w2, const float* __restrict__ w3) {
    int i = blockIdx.x * blockDim.x + threadIdx.x;
    if (i < 128*576) {
        int oc = i / 576, r = i - oc*576, ic = r / 9, k9 = r - ic*9;
        float v = w2[i];
        __nv_bfloat16 h = __float2bfloat16(v);
        int d = k9*8192 + oc*64 + ic;
        g_w2hi[d] = h;
        g_w2lo[d] = __float2bfloat16(v - __bfloat162float(h));
    } else if (i < 128*576 + 128*1152) {
        int j = i - 128*576;
        int oc = j / 1152, r = j - oc*1152, ic = r / 9, k9 = r - ic*9;
        float v = w3[j];
        __nv_bfloat16 h = __float2bfloat16(v);
        int d = k9*16384 + oc*128 + ic;
        g_w3hi[d] = h;
        g_w3lo[d] = __float2bfloat16(v - __bfloat162float(h));
    }
}

// ---------------- JAX threefry2x32, bit-exact ----------------
__device__ __forceinline__ unsigned rotl32(unsigned x, int d) { return (x << d) | (x >> (32 - d)); }
__device__ __forceinline__ void tf2x32(unsigned c0, unsigned c1, unsigned& o0, unsigned& o1) {
    const unsigned k0 = 0u, k1 = 42u;
    const unsigned k2 = 0x1BD11BDAu ^ k0 ^ k1;
    unsigned x0 = c0 + k0, x1 = c1 + k1;
#define RND(r) { x0 += x1; x1 = rotl32(x1,(r)); x1 ^= x0; }
    RND(13) RND(15) RND(26) RND(6);  x0 += k1; x1 += k2 + 1u;
    RND(17) RND(29) RND(16) RND(24); x0 += k2; x1 += k0 + 2u;
    RND(13) RND(15) RND(26) RND(6);  x0 += k0; x1 += k1 + 3u;
    RND(17) RND(29) RND(16) RND(24); x0 += k1; x1 += k2 + 4u;
    RND(13) RND(15) RND(26) RND(6);  x0 += k2; x1 += k0 + 5u;
#undef RND
    o0 = x0; o1 = x1;
}
__device__ __forceinline__ float bits_to_noise(unsigned bits) {
    float f = __uint_as_float((bits >> 9) | 0x3F800000u) - 1.0f;
    const float lo = -0.99999994f;
    float u = f * 2.0f + lo;
    u = fmaxf(lo, u);
    return 1e-4f * (1.41421356237309515f * erfinvf(u));
}

// ---------------- fused SRN: one block/image, 256 thr, 8 o per warp ------------
__global__ void __launch_bounds__(256) k_srn(const float* __restrict__ x) {
    extern __shared__ float sm[];
    float* sy = sm;            // 7056
    float* sU = sm + 7056;     // 2304
    int b = blockIdx.x;
    int tid = threadIdx.x, lane = tid & 31, warp = tid >> 5;   // warp 0..7

    for (int i = tid; i < OSRN*36; i += 256) sU[i] = g_U[i];

    const float* xb = x + b * HW28;
    unsigned jb = (unsigned)(b & 63) * 7056u;
    bool hi = (b >= 64);
    for (int l = tid; l < HW28; l += 256) {
        int h = l / 28, w = l % 28;
        float v[9]; float s = 0.f;
#pragma unroll
        for (int d = 0; d < 9; d++) {
            int yy = h + d/3 - 1, xx = w + d%3 - 1;
            float t = (yy >= 0 && yy < 28 && xx >= 0 && xx < 28) ? xb[yy*28 + xx] : 0.f;
            unsigned j = jb + (unsigned)(d*784 + l);
            unsigned o0, o1; tf2x32(j, j + (unsigned)NHALF, o0, o1);
            t += bits_to_noise(hi ? o1 : o0);
            v[d] = t; s += t;
        }
        float m = s / 9.f;
        float ss = 0.f;
#pragma unroll
        for (int d = 0; d < 9; d++) { float e = v[d] - m; ss += e*e; }
        float gg = sqrtf(ss / 8.f);
#pragma unroll
        for (int d = 0; d < 9; d++) sy[l*9 + d] = v[d] / gg;
    }
    __syncthreads();

    const float EM1f    = 0.36787944117144233f;
    const float OneMEM1 = 0.6321205588285577f;
    float s_[8], s2_[8];
#pragma unroll
    for (int oi = 0; oi < 8; oi++) { s_[oi] = 0.f; s2_[oi] = 0.f; }
    for (int pp = lane; pp < 196; pp += 32) {
        int ph = pp / 14, pw = pp % 14;
        float yv[4][9]; float ny2[4];
#pragma unroll
        for (int px = 0; px < 4; px++) {
            int l = (2*ph + (px >> 1))*28 + 2*pw + (px & 1);
            float n2 = 0.f;
#pragma unroll
            for (int i = 0; i < 9; i++) {
                float t = sy[l*9 + i];
                yv[px][i] = t;
                n2 = fmaf(t, t, n2);
            }
            ny2[px] = n2;
        }
#pragma unroll
        for (int oi = 0; oi < 8; oi++) {
            const float* U = sU + (warp*8 + oi)*36;
            float err[4];
#pragma unroll
            for (int px = 0; px < 4; px++) err[px] = ny2[px];
#pragma unroll
            for (int r = 0; r < 4; r++) {
                float t0 = 0.f, t1 = 0.f, t2 = 0.f, t3 = 0.f;
#pragma unroll
                for (int i = 0; i < 9; i++) {
                    float u = U[r*9 + i];
                    t0 = fmaf(u, yv[0][i], t0);
                    t1 = fmaf(u, yv[1][i], t1);
                    t2 = fmaf(u, yv[2][i], t2);
                    t3 = fmaf(u, yv[3][i], t3);
                }
                err[0] = fmaf(-t0, t0, err[0]);
                err[1] = fmaf(-t1, t1, err[1]);
                err[2] = fmaf(-t2, t2, err[2]);
                err[3] = fmaf(-t3, t3, err[3]);
            }
            float sum = 0.f;
#pragma unroll
            for (int px = 0; px < 4; px++) {
                float er = err[px] * (1.f/9.f);
                float A = (expf(-er) - EM1f) / OneMEM1;
                sum += (A - 0.5f);
            }
            float val = sum * 0.25f;
            g_h1[(b*OSRN + warp*8 + oi)*196 + pp] = val;
            s_[oi] += val; s2_[oi] += val*val;
        }
    }
#pragma unroll
    for (int oi = 0; oi < 8; oi++) {
        float s = s_[oi], s2 = s2_[oi];
#pragma unroll
        for (int st = 16; st > 0; st >>= 1) {
            s  += __shfl_xor_sync(0xffffffffu, s,  st);
            s2 += __shfl_xor_sync(0xffffffffu, s2, st);
        }
        if (lane == 0) {
            atomicAdd(&g_bnsum[warp*8 + oi], (double)s);
            atomicAdd(&g_bnsq[warp*8 + oi],  (double)s2);
        }
    }
}

// ============ conv2: shifted-window mma.sync. grid(2,BB), 224 thr, 2 CTA/SM =====
// A: padded bn1 window [196 rows][64 ic] bf16 hi/lo (rows 160..195 zero).
// row for pixel p, offset (dy,dx) = (phl+dy)*16 + (pwl+dx) = base + off9.
#define C2_AH 0
#define C2_AL 28224      // 196*144
#define C2_BH 56448
#define C2_BL 74880      // +128*144
#define C2_SMEM 93312

__global__ void __launch_bounds__(224, 2) k_conv2_mma(
    const float* __restrict__ in,
    const __nv_bfloat16* __restrict__ whi, const __nv_bfloat16* __restrict__ wlo,
    const float* __restrict__ bias,
    const double* __restrict__ b1sum, const double* __restrict__ b1sq,
    const float* __restrict__ g1, const float* __restrict__ be1,
    float* __restrict__ out,
    double* __restrict__ gsum, double* __restrict__ gsq) {
    extern __shared__ char dsm[];
    __shared__ float s_sc[64], s_sh[64];
    u32 sbase = s2u(dsm);
    int tid = threadIdx.x, lane = tid & 31, wm = tid >> 5;   // wm 0..6
    int mh = blockIdx.x, b = blockIdx.y;

    if (tid < 64) fold_ch(b1sum, b1sq, g1, be1, tid, (double)(BB*196), s_sc[tid], s_sh[tid]);

    float acc[16][4];
#pragma unroll
    for (int nf = 0; nf < 16; nf++)
#pragma unroll
        for (int j = 0; j < 4; j++) acc[nf][j] = 0.f;

    const float* inb = in + b * 64 * 196;
    __syncthreads();   // s_sc ready

    // ---- build padded A window once (rows 0..159 data, 160..195 zero) ----
    for (int idx = tid; idx < 64*196; idx += 224) {
        int ic = idx / 196, row = idx - ic*196;
        float v = 0.f;
        if (row < 160) {
            int iyl = row >> 4, ixl = row & 15;
            int iy = mh*8 - 1 + iyl, ix = ixl - 1;
            if ((unsigned)iy < 14u && (unsigned)ix < 14u)
                v = fmaf(s_sc[ic], inb[ic*196 + iy*14 + ix], s_sh[ic]);
        }
        __nv_bfloat16 h = __float2bfloat16(v);
        __nv_bfloat16 l = __float2bfloat16(v - __bfloat162float(h));
        *(__nv_bfloat16*)(dsm + C2_AH + row*144 + ic*2) = h;
        *(__nv_bfloat16*)(dsm + C2_AL + row*144 + ic*2) = l;
    }

    int pl = wm*16 + (lane & 15);
    int abase = (mh*112 + pl < 196) ? ((pl/14)*16 + (pl%14)) : 160;
    u32 aoff = (u32)((lane >> 4) << 4);
    int laneB   = lane & 7;
    u32 laneBof = (u32)(((lane >> 3) & 1) << 4);
    const int OFF9[9] = {0,1,2,16,17,18,32,33,34};

#pragma unroll
    for (int k9 = 0; k9 < 9; k9++) {
        __syncthreads();
        // ---- copy B for this offset (coalesced uint4) ----
        for (int idx = tid; idx < 1024; idx += 224) {
            int row = idx >> 3, c8 = idx & 7;
            int go = k9*8192 + row*64 + c8*8;
            *(uint4*)(dsm + C2_BH + row*144 + c8*16) = *(const uint4*)&whi[go];
            *(uint4*)(dsm + C2_BL + row*144 + c8*16) = *(const uint4*)&wlo[go];
        }
        __syncthreads();

        u32 aaddr = sbase + C2_AH + (u32)(abase + OFF9[k9])*144 + aoff;
#pragma unroll
        for (int ks = 0; ks < 4; ks++) {
            u32 ah[4], al[4];
            ldsm4(ah, aaddr + ks*32);
            ldsm4(al, aaddr + ks*32 + (C2_AL - C2_AH));
#pragma unroll
            for (int nf = 0; nf < 16; nf++) {
                u32 baddr = sbase + C2_BH + (u32)(nf*8 + laneB)*144 + ks*32 + laneBof;
                u32 bh0, bh1, bl0, bl1;
                ldsm2(bh0, bh1, baddr);
                ldsm2(bl0, bl1, baddr + (C2_BL - C2_BH));
                mma16816(acc[nf], ah, bh0, bh1);
                mma16816(acc[nf], ah, bl0, bl1);
                mma16816(acc[nf], al, bh0, bh1);
            }
        }
    }

    // ---- epilogue: bias + transposed store + fused bn2 stats ----
#pragma unroll
    for (int nf = 0; nf < 16; nf++) {
        int oc0 = nf*8 + (lane & 3)*2;
        float2 bv = *(const float2*)&bias[oc0];
        double ds0 = 0.0, dq0 = 0.0, ds1 = 0.0, dq1 = 0.0;
        float* c = acc[nf];
        int gp = mh*112 + wm*16 + (lane >> 2);
        if (gp < 196) {
            float v0 = c[0] + bv.x, v1 = c[1] + bv.y;
            *(float2*)&out[(b*196 + gp)*128 + oc0] = make_float2(v0, v1);
            ds0 += (double)v0; dq0 += (double)v0*(double)v0;
            ds1 += (double)v1; dq1 += (double)v1*(double)v1;
        }
        int gp2 = gp + 8;
        if (gp2 < 196) {
            float v0 = c[2] + bv.x, v1 = c[3] + bv.y;
            *(float2*)&out[(b*196 + gp2)*128 + oc0] = make_float2(v0, v1);
            ds0 += (double)v0; dq0 += (double)v0*(double)v0;
            ds1 += (double)v1; dq1 += (double)v1*(double)v1;
        }
#pragma unroll
        for (int st = 4; st <= 16; st <<= 1) {
            ds0 += __shfl_xor_sync(0xffffffffu, ds0, st);
            dq0 += __shfl_xor_sync(0xffffffffu, dq0, st);
            ds1 += __shfl_xor_sync(0xffffffffu, ds1, st);
            dq1 += __shfl_xor_sync(0xffffffffu, dq1, st);
        }
        if ((lane >> 2) == 0) {
            atomicAdd(&gsum[oc0],     ds0);
            atomicAdd(&gsq[oc0],      dq0);
            atomicAdd(&gsum[oc0 + 1], ds1);
            atomicAdd(&gsq[oc0 + 1],  dq1);
        }
    }
}

// ============ conv3: shifted-window mma.sync. grid(2,BB), 128 thr ============
// A: padded h3 window [102 rows][128 ic] (rows 81..101 zero); row=(ph+dy)*9+(pw+dx).
#define C3_AH 0
#define C3_AL 27744      // 102*272
#define C3_BH 55488
#define C3_BL 72896      // +64*272
#define C3_SMEM 90304

__global__ void __launch_bounds__(128, 2) k_conv3_mma(
    const float* __restrict__ in,
    const __nv_bfloat16* __restrict__ whi, const __nv_bfloat16* __restrict__ wlo,
    const float* __restrict__ bias,
    float* __restrict__ out,
    double* __restrict__ gsum, double* __restrict__ gsq) {
    extern __shared__ char dsm[];
    u32 sbase = s2u(dsm);
    int tid = threadIdx.x, lane = tid & 31, wm = tid >> 5;   // wm 0..3
    int nh = blockIdx.x, b = blockIdx.y;

    float acc[8][4];
#pragma unroll
    for (int nf = 0; nf < 8; nf++)
#pragma unroll
        for (int j = 0; j < 4; j++) acc[nf][j] = 0.f;

    const float* inb = in + b * 128 * 49;

    // ---- build padded A window once ----
    for (int idx = tid; idx < 128*102; idx += 128) {
        int ic = idx / 102, row = idx - ic*102;
        float v = 0.f;
        if (row < 81) {
            int iyl = row / 9, ixl = row - iyl*9;
            int iy = iyl - 1, ix = ixl - 1;
            if ((unsigned)iy < 7u && (unsigned)ix < 7u)
                v = inb[ic*49 + iy*7 + ix];
        }
        __nv_bfloat16 h = __float2bfloat16(v);
        __nv_bfloat16 l = __float2bfloat16(v - __bfloat162float(h));
        *(__nv_bfloat16*)(dsm + C3_AH + row*272 + ic*2) = h;
        *(__nv_bfloat16*)(dsm + C3_AL + row*272 + ic*2) = l;
    }

    int pl = wm*16 + (lane & 15);
    int abase = (pl < 49) ? ((pl/7)*9 + (pl%7)) : 81;
    u32 aoff = (u32)((lane >> 4) << 4);
    int laneB   = lane & 7;
    u32 laneBof = (u32)(((lane >> 3) & 1) << 4);
    const int OFF9[9] = {0,1,2,9,10,11,18,19,20};

#pragma unroll
    for (int k9 = 0; k9 < 9; k9++) {
        __syncthreads();
        // ---- copy B for this offset (64 oc of this nh-half) ----
        for (int idx = tid; idx < 1024; idx += 128) {
            int row = idx >> 4, c16 = idx & 15;
            int go = k9*16384 + (nh*64 + row)*128 + c16*8;
            *(uint4*)(dsm + C3_BH + row*272 + c16*16) = *(const uint4*)&whi[go];
            *(uint4*)(dsm + C3_BL + row*272 + c16*16) = *(const uint4*)&wlo[go];
        }
        __syncthreads();

        u32 aaddr = sbase + C3_AH + (u32)(abase + OFF9[k9])*272 + aoff;
#pragma unroll
        for (int ks = 0; ks < 8; ks++) {
            u32 ah[4], al[4];
            ldsm4(ah, aaddr + ks*32);
            ldsm4(al, aaddr + ks*32 + (C3_AL - C3_AH));
#pragma unroll
            for (int nf = 0; nf < 8; nf++) {
                u32 baddr = sbase + C3_BH + (u32)(nf*8 + laneB)*272 + ks*32 + laneBof;
                u32 bh0, bh1, bl0, bl1;
                ldsm2(bh0, bh1, baddr);
                ldsm2(bl0, bl1, baddr + (C3_BL - C3_BH));
                mma16816(acc[nf], ah, bh0, bh1);
                mma16816(acc[nf], ah, bl0, bl1);
                mma16816(acc[nf], al, bh0, bh1);
            }
        }
    }

#pragma unroll
    for (int nf = 0; nf < 8; nf++) {
        int oc0 = nh*64 + nf*8 + (lane & 3)*2;
        float2 bv = *(const float2*)&bias[oc0];
        double ds0 = 0.0, dq0 = 0.0, ds1 = 0.0, dq1 = 0.0;
        float* c = acc[nf];
        int prow = wm*16 + (lane >> 2);
        if (prow < 49) {
            float v0 = c[0] + bv.x, v1 = c[1] + bv.y;
            *(float2*)&out[(b*49 + prow)*128 + oc0] = make_float2(v0, v1);
            ds0 += (double)v0; dq0 += (double)v0*(double)v0;
            ds1 += (double)v1; dq1 += (double)v1*(double)v1;
        }
        int prow2 = prow + 8;
        if (prow2 < 49) {
            float v0 = c[2] + bv.x, v1 = c[3] + bv.y;
            *(float2*)&out[(b*49 + prow2)*128 + oc0] = make_float2(v0, v1);
            ds0 += (double)v0; dq0 += (double)v0*(double)v0;
            ds1 += (double)v1; dq1 += (double)v1*(double)v1;
        }
#pragma unroll
        for (int st = 4; st <= 16; st <<= 1) {
            ds0 += __shfl_xor_sync(0xffffffffu, ds0, st);
            dq0 += __shfl_xor_sync(0xffffffffu, dq0, st);
            ds1 += __shfl_xor_sync(0xffffffffu, ds1, st);
            dq1 += __shfl_xor_sync(0xffffffffu, dq1, st);
        }
        if ((lane >> 2) == 0) {
            atomicAdd(&gsum[oc0],     ds0);
            atomicAdd(&gsq[oc0],      dq0);
            atomicAdd(&gsum[oc0 + 1], ds1);
            atomicAdd(&gsq[oc0 + 1],  dq1);
        }
    }
}

// ---------------- direct 3x3 conv (SIMT) for conv4 ----------------
template<int HH, int WW, int IC, int BPB, int PSLOTS, int PITER>
__global__ void k_conv(const float* __restrict__ in, const float* __restrict__ wt,
                       const float* __restrict__ bias,
                       float* __restrict__ out,
                       double* __restrict__ gsum, double* __restrict__ gsq) {
    constexpr int OC = 128, OCB = 16, PW = WW + 2, TILE = (HH+2)*PW, NPIX = HH*WW, ICC = 8;
    constexpr int REDW = (PSLOTS < 32) ? PSLOTS : 32;
    __shared__ float sIn[BPB][ICC][TILE];
    __shared__ float sW[ICC][9][OCB];
    __shared__ double sS[OCB], sQ2[OCB];
    int tid = threadIdx.x, lane = tid & 31;
    int pslot = tid % PSLOTS;
    int oh = (tid / PSLOTS) & 1;
    int bl = tid / (2*PSLOTS);
    int b0 = blockIdx.x * BPB;
    int oc0 = blockIdx.y * OCB;

    int hh[PITER], wc[PITER]; bool act[PITER];
#pragma unroll
    for (int pi = 0; pi < PITER; pi++) {
        int p = pslot + pi*PSLOTS;
        act[pi] = (p < NPIX);
        if (!act[pi]) p = 0;
        hh[pi] = p / WW; wc[pi] = p % WW;
    }
    float acc[PITER][8];
#pragma unroll
    for (int pi = 0; pi < PITER; pi++)
#pragma unroll
        for (int j = 0; j < 8; j++) acc[pi][j] = 0.f;

    for (int ic0 = 0; ic0 < IC; ic0 += ICC) {
        __syncthreads();
        for (int idx = tid; idx < BPB*ICC*TILE; idx += blockDim.x) {
            int t = idx % TILE; int ic = (idx/TILE) % ICC; int bb = idx/(TILE*ICC);
            int y = t / PW, xx = t % PW;
            float v = 0.f;
            if (y >= 1 && y <= HH && xx >= 1 && xx <= WW)
                v = in[((b0+bb)*IC + ic0+ic)*NPIX + (y-1)*WW + (xx-1)];
            sIn[bb][ic][t] = v;
        }
        for (int idx = tid; idx < ICC*9*OCB; idx += blockDim.x) {
            int ol = idx % OCB; int k = (idx/OCB) % 9; int ic = idx/(OCB*9);
            sW[ic][k][ol] = wt[(oc0+ol)*(IC*9) + (ic0+ic)*9 + k];
        }
        __syncthreads();
#pragma unroll
        for (int ic = 0; ic < ICC; ic++) {
#pragma unroll
            for (int k = 0; k < 9; k++) {
                int dy = k/3, dx = k%3;
                float4 w0 = *(const float4*)&sW[ic][k][oh*8];
                float4 w1 = *(const float4*)&sW[ic][k][oh*8 + 4];
#pragma unroll
                for (int pi = 0; pi < PITER; pi++) {
                    float v = sIn[bl][ic][(hh[pi]+dy)*PW + wc[pi] + dx];
                    acc[pi][0] = fmaf(v, w0.x, acc[pi][0]);
                    acc[pi][1] = fmaf(v, w0.y, acc[pi][1]);
                    acc[pi][2] = fmaf(v, w0.z, acc[pi][2]);
                    acc[pi][3] = fmaf(v, w0.w, acc[pi][3]);
                    acc[pi][4] = fmaf(v, w1.x, acc[pi][4]);
                    acc[pi][5] = fmaf(v, w1.y, acc[pi][5]);
                    acc[pi][6] = fmaf(v, w1.z, acc[pi][6]);
                    acc[pi][7] = fmaf(v, w1.w, acc[pi][7]);
                }
            }
        }
    }

    __syncthreads();
    if (tid < OCB) { sS[tid] = 0.0; sQ2[tid] = 0.0; }
    __syncthreads();

    float bv[8];
#pragma unroll
    for (int j = 0; j < 8; j++) bv[j] = bias[oc0 + oh*8 + j];

    double ds[8], dq[8];
#pragma unroll
    for (int j = 0; j < 8; j++) { ds[j] = 0.0; dq[j] = 0.0; }
#pragma unroll
    for (int pi = 0; pi < PITER; pi++) if (act[pi]) {
        int p = pslot + pi*PSLOTS;
#pragma unroll
        for (int j = 0; j < 8; j++) {
            float v = acc[pi][j] + bv[j];
            out[((b0+bl)*OC + oc0 + oh*8 + j)*NPIX + p] = v;
            double dv = (double)v;
            ds[j] += dv; dq[j] += dv*dv;
        }
    }
#pragma unroll
    for (int st = REDW/2; st > 0; st >>= 1)
#pragma unroll
        for (int j = 0; j < 8; j++) {
            ds[j] += __shfl_xor_sync(0xffffffffu, ds[j], st);
            dq[j] += __shfl_xor_sync(0xffffffffu, dq[j], st);
        }
    if ((lane & (REDW-1)) == 0)
#pragma unroll
        for (int j = 0; j < 8; j++) {
            atomicAdd(&sS[oh*8 + j],  ds[j]);
            atomicAdd(&sQ2[oh*8 + j], dq[j]);
        }
    __syncthreads();
    if (tid < OCB) {
        atomicAdd(&gsum[oc0 + tid], sS[tid]);
        atomicAdd(&gsq[oc0 + tid],  sQ2[tid]);
    }
}

// ---------------- bn2+relu+avgpool2 (reads h2 [b][pix][oc], inline fold) --------
__global__ void k_avgpool_bn_relu(const float* __restrict__ src,
                                  const double* __restrict__ bsum, const double* __restrict__ bsq,
                                  const float* __restrict__ gam, const float* __restrict__ bet,
                                  float* __restrict__ dst) {
    const int HO = 7;
    int i = blockIdx.x * blockDim.x + threadIdx.x;
    if (i >= BB*128*HO*HO) return;
    int c = i & 127;
    int j = i >> 7;
    int pw = j % 7, ph = (j/7) % 7, bb = j/49;
    float a, b2;
    fold_ch(bsum, bsq, gam, bet, c, (double)(BB*196), a, b2);
    float sum = 0.f;
#pragma unroll
    for (int dy = 0; dy < 2; dy++)
#pragma unroll
    for (int dx = 0; dx < 2; dx++) {
        int pix = (2*ph+dy)*14 + 2*pw+dx;
        sum += fmaxf(0.f, fmaf(a, src[(bb*196 + pix)*128 + c], b2));
    }
    dst[(bb*128 + c)*49 + ph*7 + pw] = sum * 0.25f;
}

// ---------------- bn3+relu+maxpool2(pad1) (reads h4 [b][pix][oc], inline fold) --
__global__ void k_maxpool3(const float* __restrict__ src,
                           const double* __restrict__ bsum, const double* __restrict__ bsq,
                           const float* __restrict__ gam, const float* __restrict__ bet,
                           float* __restrict__ dst) {
    int i = blockIdx.x * blockDim.x + threadIdx.x;
    if (i >= BB*128*16) return;
    int pw = i % 4, ph = (i/4) % 4, c = (i/16) % 128, bb = i/(16*128);
    float a, b2;
    fold_ch(bsum, bsq, gam, bet, c, (double)(BB*49), a, b2);
    float m = -1e30f;
#pragma unroll
    for (int dy = 0; dy < 2; dy++) {
        int y = 2*ph - 1 + dy;
        if (y < 0 || y > 6) continue;
#pragma unroll
        for (int dx = 0; dx < 2; dx++) {
            int x = 2*pw - 1 + dx;
            if (x < 0 || x > 6) continue;
            m = fmaxf(m, fmaxf(0.f, fmaf(a, src[(bb*49 + y*7 + x)*128 + c], b2)));
        }
    }
    dst[i] = m;
}

// ---------------- bn4+relu+maxpool4 -> x_errs (inline fold) ----------------
__global__ void k_final_pool(const float* __restrict__ src,
                             const double* __restrict__ bsum, const double* __restrict__ bsq,
                             const float* __restrict__ gam, const float* __restrict__ bet,
                             float* __restrict__ out_err) {
    int i = blockIdx.x * blockDim.x + threadIdx.x;
    if (i >= BB*128) return;
    int c = i % 128;
    const float* p = src + i*16;
    float a, b2;
    fold_ch(bsum, bsq, gam, bet, c, (double)(BB*16), a, b2);
    float m = -1e30f;
#pragma unroll
    for (int k = 0; k < 16; k++) m = fmaxf(m, fmaxf(0.f, fmaf(a, p[k], b2)));
    g_xe[i] = m;
    out_err[i] = m;
}

// ---------------- fc1 ----------------
__global__ void k_fc1(const float* __restrict__ w, const float* __restrict__ bias) {
    __shared__ float xs[128];
    int b = blockIdx.x, o = threadIdx.x;
    xs[o] = g_xe[b*128 + o];
    __syncthreads();
    float a = bias[o];
#pragma unroll 8
    for (int i = 0; i < 128; i++) a = fmaf(w[o*128 + i], xs[i], a);
    g_r[b*128 + o] = a;
}

// ---------------- bnfc ----------------
__global__ void k_bnfc(const float* __restrict__ gam, const float* __restrict__ bet) {
    int c = threadIdx.x;
    double s = 0, s2 = 0;
    for (int b = 0; b < 128; b++) { double v = (double)g_r[b*128 + c]; s += v; s2 += v*v; }
    double m = s/128.0, var = s2/128.0 - m*m;
    double inv = 1.0 / sqrt(var + 1e-5);
    double scv = (double)gam[c] * inv;
    g_scf[c] = (float)scv;
    g_shf[c] = (float)((double)bet[c] - m*scv);
}

// ---------------- fc2 ----------------
__global__ void k_fc2(const float* __restrict__ w, const float* __restrict__ bias,
                      float* __restrict__ out) {
    __shared__ float as[128];
    int b = blockIdx.x, t = threadIdx.x;
    as[t] = fmaxf(0.f, fmaf(g_scf[t], g_r[b*128 + t], g_shf[t]));
    __syncthreads();
    if (t < 10) {
        float a = bias[t];
#pragma unroll 8
        for (int i = 0; i < 128; i++) a = fmaf(w[t*128 + i], as[i], a);
        out[b*10 + t] = a;
    }
}

// ================================================================================
extern "C" void kernel_launch(void* const* d_in, const int* in_sizes, int n_in,
                              void* d_out, int out_size) {
    const float* x       = (const float*)d_in[0];
    const float* srn_w   = (const float*)d_in[1];
    const float* conv2_w = (const float*)d_in[2];
    const float* conv2_b = (const float*)d_in[3];
    const float* conv3_w = (const float*)d_in[4];
    const float* conv3_b = (const float*)d_in[5];
    const float* conv4_w = (const float*)d_in[6];
    const float* conv4_b = (const float*)d_in[7];
    const float* fc1_w   = (const float*)d_in[8];
    const float* fc1_b   = (const float*)d_in[9];
    const float* fc2_w   = (const float*)d_in[10];
    const float* fc2_b   = (const float*)d_in[11];
    const float* bn1_g   = (const float*)d_in[12];
    const float* bn1_b   = (const float*)d_in[13];
    const float* bn2_g   = (const float*)d_in[14];
    const float* bn2_b   = (const float*)d_in[15];
    const float* bn3_g   = (const float*)d_in[16];
    const float* bn3_b   = (const float*)d_in[17];
    const float* bn4_g   = (const float*)d_in[18];
    const float* bn4_b   = (const float*)d_in[19];
    const float* bnfc_g  = (const float*)d_in[20];
    const float* bnfc_b  = (const float*)d_in[21];
    float* out = (float*)d_out;

    float *h1, *h2, *h3, *h4, *h5, *h6;
    double *bsum, *bsq;
    __nv_bfloat16 *w2hi, *w2lo, *w3hi, *w3lo;
    { void* p;
      cudaGetSymbolAddress(&p, g_h1);  h1  = (float*)p;
      cudaGetSymbolAddress(&p, g_h2);  h2  = (float*)p;
      cudaGetSymbolAddress(&p, g_h3);  h3  = (float*)p;
      cudaGetSymbolAddress(&p, g_h4);  h4  = (float*)p;
      cudaGetSymbolAddress(&p, g_h5);  h5  = (float*)p;
      cudaGetSymbolAddress(&p, g_h6);  h6  = (float*)p;
      cudaGetSymbolAddress(&p, g_bnsum); bsum = (double*)p;
      cudaGetSymbolAddress(&p, g_bnsq);  bsq  = (double*)p;
      cudaGetSymbolAddress(&p, g_w2hi); w2hi = (__nv_bfloat16*)p;
      cudaGetSymbolAddress(&p, g_w2lo); w2lo = (__nv_bfloat16*)p;
      cudaGetSymbolAddress(&p, g_w3hi); w3hi = (__nv_bfloat16*)p;
      cudaGetSymbolAddress(&p, g_w3lo); w3lo = (__nv_bfloat16*)p;
    }

    cudaFuncSetAttribute(k_conv2_mma, cudaFuncAttributeMaxDynamicSharedMemorySize, C2_SMEM);
    cudaFuncSetAttribute(k_conv3_mma, cudaFuncAttributeMaxDynamicSharedMemorySize, C3_SMEM);

    k_init<<<1, 512>>>(srn_w);                                              // 1
    k_wsplit<<<(128*576 + 128*1152 + 255)/256, 256>>>(conv2_w, conv3_w);    // 2
    k_srn<<<BB, 256, (7056 + 2304)*sizeof(float)>>>(x);                     // 3
    { dim3 g(2, BB);
      k_conv2_mma<<<g, 224, C2_SMEM>>>(h1, w2hi, w2lo, conv2_b,
                                       bsum, bsq, bn1_g, bn1_b, h2,
                                       bsum + 128, bsq + 128); }            // 4 (profiled)
    k_avgpool_bn_relu<<<(BB*128*49 + 255)/256, 256>>>(h2, bsum + 128, bsq + 128,
                                                      bn2_g, bn2_b, h3);
    { dim3 g(2, BB);
      k_conv3_mma<<<g, 128, C3_SMEM>>>(h3, w3hi, w3lo, conv3_b, h4,
                                       bsum + 256, bsq + 256); }
    k_maxpool3<<<(BB*128*16 + 255)/256, 256>>>(h4, bsum + 256, bsq + 256,
                                               bn3_g, bn3_b, h5);
    { dim3 g(BB/8, 8); k_conv<4,4,128,8,16,1><<<g, 256>>>(h5, conv4_w, conv4_b, h6,
                                                          bsum + 384, bsq + 384); }
    k_final_pool<<<(BB*128 + 255)/256, 256>>>(h6, bsum + 384, bsq + 384,
                                              bn4_g, bn4_b, out + 1280);
    k_fc1<<<BB, 128>>>(fc1_w, fc1_b);
    k_bnfc<<<1, 128>>>(bnfc_g, bnfc_b);
    k_fc2<<<BB, 128>>>(fc2_w, fc2_b, out);
}